// round 7
// baseline (speedup 1.0000x reference)
#include <cuda_runtime.h>
#include <cuda_fp16.h>
#include <stdint.h>

#define NTOK   262144
#define NSLOT  524288
#define DIN    128
#define DOUT   128
#define NEXP   8
#define TM     128            // slot rows per tile
#define NT     (NSLOT / TM)   // 4096 tiles
#define GRID   148
#define NTHR   512
#define SAR    132            // Araw stride (floats), 16B-aligned rows
#define SBW    130            // Bs32 stride (floats), 8B-aligned rows

typedef unsigned long long ull;

__device__ float g_ybuf[(size_t)NSLOT * DOUT];   // gate-scaled per-slot outputs

// ---------------------------------------------------------------------------
// helpers
// ---------------------------------------------------------------------------
__device__ __forceinline__ uint32_t smem_u32(const void* p) {
    uint32_t a;
    asm("{ .reg .u64 t; cvta.to.shared.u64 t, %1; cvt.u32.u64 %0, t; }" : "=r"(a) : "l"(p));
    return a;
}
__device__ __forceinline__ uint32_t pack_h2(float x, float y) {
    uint32_t u;
    asm("cvt.rn.f16x2.f32 %0, %1, %2;" : "=r"(u) : "f"(y), "f"(x));
    return u;
}
__device__ __forceinline__ void cp16(uint32_t dst, const void* src) {
    asm volatile("cp.async.ca.shared.global [%0], [%1], 16;" :: "r"(dst), "l"(src) : "memory");
}
#define CP_COMMIT() asm volatile("cp.async.commit_group;" ::: "memory")
#define CP_WAIT0()  asm volatile("cp.async.wait_group 0;" ::: "memory")

__device__ __forceinline__ void mma_f16(float* d, const uint32_t* a, uint32_t b0, uint32_t b1) {
    asm volatile("mma.sync.aligned.m16n8k16.row.col.f32.f16.f16.f32 "
                 "{%0,%1,%2,%3}, {%4,%5,%6,%7}, {%8,%9}, {%0,%1,%2,%3};"
                 : "+f"(d[0]), "+f"(d[1]), "+f"(d[2]), "+f"(d[3])
                 : "r"(a[0]), "r"(a[1]), "r"(a[2]), "r"(a[3]), "r"(b0), "r"(b1));
}
__device__ __forceinline__ void ffma2(ull& acc, ull x, ull w) {
    asm("fma.rn.f32x2 %0, %1, %2, %0;" : "+l"(acc) : "l"(x), "l"(w));
}

// ---------------------------------------------------------------------------
// Hybrid persistent grouped-GEMM: tensor warps (0-7) do N 0..63 via fp16 HMMA,
// scalar warps (8-15) do N 64..127 via fp32 f32x2 FMA. 512 threads, 1 CTA/SM.
// smem: Araw f32[128][SAR] | As_frag uint4[2048] | B_frag uint4[1024]
//       | Bs32 f32[64][SBW]
// ---------------------------------------------------------------------------
__global__ void __launch_bounds__(NTHR, 1)
k_moe(const float* __restrict__ inputs,
      const float* __restrict__ weight,   // [E][DOUT][DIN] = W[n][k] row-major
      const float* __restrict__ gates,    // flat [NSLOT]
      const int*   __restrict__ sei,
      const int*   __restrict__ ssi)
{
    extern __shared__ float smraw[];
    float* Araw    = smraw;                              // 128*SAR f32
    uint4* As_frag = (uint4*)(smraw + 128 * SAR);        // 2048 uint4
    uint4* B_frag  = As_frag + 2048;                     // 1024 uint4 (np 0..3)
    float* Bs32    = (float*)(B_frag + 1024);            // [64][SBW] f32 (n 64..127)

    __shared__ int   ss2[2][TM];
    __shared__ float gt2[2][TM];
    __shared__ int   ex2[2][TM];
    __shared__ int   seg_e[NEXP + 1];
    __shared__ int   seg_n;

    const int tid  = threadIdx.x;
    const int lane = tid & 31;
    const int wid  = tid >> 5;        // 0..15
    const int gr   = lane >> 2;       // 0..7
    const int tc   = lane & 3;        // 0..3
    // tensor mapping (wid 0..7)
    const int wm   = wid >> 1;        // 0..3 -> rows wm*32
    const int wn   = wid & 1;         // 0..1 -> cols wn*32
    // scalar mapping (wid 8..15)
    const int tids = tid - 256;                // 0..255
    const int rblk = tids >> 3;                // 0..31 -> rows rblk*4
    const int cblk = tids & 7;                 // 0..7  -> cols 64 + cblk*8

    // ---- prologue: metadata + first A prefetch ----
    int t0 = blockIdx.x;
    if (tid < TM) {
        const int ss = ssi[t0 * TM + tid];
        ss2[0][tid] = ss;
        gt2[0][tid] = gates[ss];
        ex2[0][tid] = sei[t0 * TM + tid];
    }
    __syncthreads();
    {
        const uint32_t abase = smem_u32(Araw);
        #pragma unroll
        for (int it = 0; it < 8; ++it) {
            const int idx = tid + NTHR * it;          // 4096 float4 units
            const int m = idx >> 5, q = (idx & 31) * 4;
            cp16(abase + (uint32_t)(m * SAR + q) * 4,
                 inputs + (size_t)(ss2[0][m] >> 1) * DIN + q);
        }
    }
    CP_COMMIT();

    int par = 0;
    int B_cur = -1;

    for (int t = t0; t < NT; t += GRID) {
        CP_WAIT0();
        __syncthreads();   // Araw ready

        // ---- cvt Araw(fp32) -> As_frag(fp16 fragments), all 16 warps ----
        {
            const int R = wid >> 1;
            const int ks0 = (wid & 1) * 4;
            const int row = R * 16 + gr;
            #pragma unroll
            for (int i = 0; i < 4; ++i) {
                const int ks = ks0 + i;
                const int c0 = ks * 16 + tc * 2;
                const float2 v00 = *(const float2*)(Araw + row * SAR + c0);
                const float2 v10 = *(const float2*)(Araw + (row + 8) * SAR + c0);
                const float2 v01 = *(const float2*)(Araw + row * SAR + c0 + 8);
                const float2 v11 = *(const float2*)(Araw + (row + 8) * SAR + c0 + 8);
                uint4 f;
                f.x = pack_h2(v00.x, v00.y);
                f.y = pack_h2(v10.x, v10.y);
                f.z = pack_h2(v01.x, v01.y);
                f.w = pack_h2(v11.x, v11.y);
                As_frag[(R * 8 + ks) * 32 + lane] = f;
            }
        }

        // ---- next-tile metadata + segment list ----
        const int tn = t + GRID;
        if (tid < TM && tn < NT) {
            const int ss = ssi[tn * TM + tid];
            ss2[par ^ 1][tid] = ss;
            gt2[par ^ 1][tid] = gates[ss];
            ex2[par ^ 1][tid] = sei[tn * TM + tid];
        }
        if (tid == 0) {
            int ns = 0, e = ex2[par][0];
            seg_e[ns++] = e;
            for (int i = 1; i < TM; ++i) {
                const int ei = ex2[par][i];
                if (ei != e) { e = ei; seg_e[ns++] = e; }
            }
            seg_n = ns;
        }
        __syncthreads();   // As_frag ready; seg list ready (Araw still live!)

        // ---- expert segments ----
        const int nseg = seg_n;
        for (int s = 0; s < nseg; ++s) {
            const int e = seg_e[s];
            if (e != B_cur) {
                __syncthreads();   // everyone done reading old B tiles
                if (wid < 8) {
                    // warps 0-7: fp16 fragments for n8 blocks 0..7 (N 0..63)
                    const int b = wid;
                    const float* Wrow = weight + (size_t)e * DOUT * DIN + (b * 8 + gr) * DIN;
                    uint2* dst2 = (uint2*)B_frag;
                    #pragma unroll
                    for (int ks = 0; ks < 8; ++ks) {
                        const int k0 = ks * 16 + tc * 2;
                        const float2 w0 = *(const float2*)(Wrow + k0);
                        const float2 w1 = *(const float2*)(Wrow + k0 + 8);
                        uint2 f;
                        f.x = pack_h2(w0.x, w0.y);
                        f.y = pack_h2(w1.x, w1.y);
                        dst2[(((b >> 1) * 8 + ks) * 32 + lane) * 2 + (b & 1)] = f;
                    }
                } else {
                    // warps 8-15: fp32 copy of W rows 64..127 into Bs32
                    const int ws = wid - 8;
                    const float* Wb = weight + (size_t)e * DOUT * DIN;
                    #pragma unroll
                    for (int it = 0; it < 8; ++it) {
                        const int idx = lane + 32 * it;   // 256 f4 units
                        const int rl = idx >> 5, q = (idx & 31) * 4;
                        const int n = 64 + ws * 8 + rl;
                        const float4 v = *(const float4*)(Wb + n * DIN + q);
                        float* d = Bs32 + (n - 64) * SBW + q;
                        *(float2*)(d)     = make_float2(v.x, v.y);
                        *(float2*)(d + 2) = make_float2(v.z, v.w);
                    }
                }
                B_cur = e;
                __syncthreads();
            }

            if (wid < 8) {
                // ---- tensor: 32(M) x 32(N) warp tile over N 0..63 ----
                float acc[2][4][4];
                #pragma unroll
                for (int mt = 0; mt < 2; ++mt)
                    #pragma unroll
                    for (int nt = 0; nt < 4; ++nt)
                        #pragma unroll
                        for (int j = 0; j < 4; ++j) acc[mt][nt][j] = 0.f;

                const int R0  = wm * 2;
                const int np0 = wn * 2;
                #pragma unroll
                for (int ks = 0; ks < 8; ++ks) {
                    const uint4 A0 = As_frag[(R0 * 8 + ks) * 32 + lane];
                    const uint4 A1 = As_frag[((R0 + 1) * 8 + ks) * 32 + lane];
                    const uint4 B0 = B_frag[(np0 * 8 + ks) * 32 + lane];
                    const uint4 B1 = B_frag[((np0 + 1) * 8 + ks) * 32 + lane];
                    const uint32_t a0[4] = {A0.x, A0.y, A0.z, A0.w};
                    const uint32_t a1[4] = {A1.x, A1.y, A1.z, A1.w};
                    mma_f16(acc[0][0], a0, B0.x, B0.y);
                    mma_f16(acc[0][1], a0, B0.z, B0.w);
                    mma_f16(acc[0][2], a0, B1.x, B1.y);
                    mma_f16(acc[0][3], a0, B1.z, B1.w);
                    mma_f16(acc[1][0], a1, B0.x, B0.y);
                    mma_f16(acc[1][1], a1, B0.z, B0.w);
                    mma_f16(acc[1][2], a1, B1.x, B1.y);
                    mma_f16(acc[1][3], a1, B1.z, B1.w);
                }

                #pragma unroll
                for (int mt = 0; mt < 2; ++mt) {
                    #pragma unroll
                    for (int half = 0; half < 2; ++half) {
                        const int m = wm * 32 + mt * 16 + gr + half * 8;
                        if (ex2[par][m] != e) continue;
                        const float g = gt2[par][m];
                        float* dst = g_ybuf + (size_t)ss2[par][m] * DOUT + wn * 32 + 2 * tc;
                        #pragma unroll
                        for (int nt = 0; nt < 4; ++nt) {
                            float2 o;
                            o.x = acc[mt][nt][half * 2 + 0] * g;
                            o.y = acc[mt][nt][half * 2 + 1] * g;
                            *(float2*)(dst + nt * 8) = o;
                        }
                    }
                }
            } else {
                // ---- scalar: rows rblk*4..+3, cols 64+cblk*8..+7, fp32 ----
                ull acc2[4][8];
                #pragma unroll
                for (int r = 0; r < 4; ++r)
                    #pragma unroll
                    for (int c = 0; c < 8; ++c) acc2[r][c] = 0ull;

                const float* xrow = Araw + (rblk * 4) * SAR;
                const float* wrow = Bs32 + (cblk * 8) * SBW;
                #pragma unroll 4
                for (int kp = 0; kp < 64; ++kp) {
                    const int k0 = kp * 2;
                    ull x2[4], w2[8];
                    #pragma unroll
                    for (int r = 0; r < 4; ++r)
                        x2[r] = *(const ull*)(xrow + r * SAR + k0);
                    #pragma unroll
                    for (int c = 0; c < 8; ++c)
                        w2[c] = *(const ull*)(wrow + c * SBW + k0);
                    #pragma unroll
                    for (int r = 0; r < 4; ++r)
                        #pragma unroll
                        for (int c = 0; c < 8; ++c)
                            ffma2(acc2[r][c], x2[r], w2[c]);
                }

                #pragma unroll
                for (int r = 0; r < 4; ++r) {
                    const int m = rblk * 4 + r;
                    if (ex2[par][m] != e) continue;
                    const float g = gt2[par][m];
                    float4 o0, o1;
                    {
                        const float2* a0 = (const float2*)&acc2[r][0];
                        const float2* a1 = (const float2*)&acc2[r][1];
                        const float2* a2 = (const float2*)&acc2[r][2];
                        const float2* a3 = (const float2*)&acc2[r][3];
                        o0.x = (a0->x + a0->y) * g;
                        o0.y = (a1->x + a1->y) * g;
                        o0.z = (a2->x + a2->y) * g;
                        o0.w = (a3->x + a3->y) * g;
                        const float2* a4 = (const float2*)&acc2[r][4];
                        const float2* a5 = (const float2*)&acc2[r][5];
                        const float2* a6 = (const float2*)&acc2[r][6];
                        const float2* a7 = (const float2*)&acc2[r][7];
                        o1.x = (a4->x + a4->y) * g;
                        o1.y = (a5->x + a5->y) * g;
                        o1.z = (a6->x + a6->y) * g;
                        o1.w = (a7->x + a7->y) * g;
                    }
                    float* dst = g_ybuf + (size_t)ss2[par][m] * DOUT + 64 + cblk * 8;
                    *(float4*)(dst)     = o0;
                    *(float4*)(dst + 4) = o1;
                }
            }
        }

        __syncthreads();   // all reads of Araw / frags done before overwrite

        // ---- prefetch next tile's A into Araw ----
        if (tn < NT) {
            const uint32_t abase = smem_u32(Araw);
            #pragma unroll
            for (int it = 0; it < 8; ++it) {
                const int idx = tid + NTHR * it;
                const int m = idx >> 5, q = (idx & 31) * 4;
                cp16(abase + (uint32_t)(m * SAR + q) * 4,
                     inputs + (size_t)(ss2[par ^ 1][m] >> 1) * DIN + q);
            }
        }
        CP_COMMIT();
        par ^= 1;
    }
}

// ---------------------------------------------------------------------------
// Combine: out[t] = ybuf[2t] + ybuf[2t+1] (gates already applied)
// ---------------------------------------------------------------------------
__global__ void k_combine(float* __restrict__ out) {
    const int i = blockIdx.x * 256 + threadIdx.x;   // 0 .. NTOK*32-1
    const int t = i >> 5;
    const int q = (i & 31) * 4;
    const float* a = g_ybuf + (size_t)(2 * t) * DOUT + q;
    const float4 va = *(const float4*)a;
    const float4 vb = *(const float4*)(a + DOUT);
    float4 o;
    o.x = va.x + vb.x; o.y = va.y + vb.y;
    o.z = va.z + vb.z; o.w = va.w + vb.w;
    *(float4*)(out + (size_t)t * DOUT + q) = o;
}

// ---------------------------------------------------------------------------
extern "C" void kernel_launch(void* const* d_in, const int* in_sizes, int n_in,
                              void* d_out, int out_size)
{
    const float* inputs = (const float*)d_in[0];
    const float* weight = (const float*)d_in[1];
    const float* gates  = (const float*)d_in[2];

    int idxs[2] = {-1, -1};
    int found = 0;
    for (int i = 3; i < n_in && found < 2; ++i) {
        if (in_sizes[i] == 1) continue;   // scalar k
        idxs[found++] = i;
    }
    const int* sei = (const int*)d_in[idxs[0]];
    const int* ssi = (const int*)d_in[idxs[1]];
    float* out = (float*)d_out;
    (void)out_size;

    // Araw 67584 + As_frag 32768 + B_frag 16384 + Bs32 64*130*4=33280 = 150016
    const int smem = 128 * SAR * 4 + 2048 * 16 + 1024 * 16 + 64 * SBW * 4;
    cudaFuncSetAttribute(k_moe, cudaFuncAttributeMaxDynamicSharedMemorySize, smem);

    k_moe<<<GRID, NTHR, smem>>>(inputs, weight, gates, sei, ssi);
    k_combine<<<(NTOK * 32) / 256, 256>>>(out);
}

// round 8
// speedup vs baseline: 1.5646x; 1.5646x over previous
#include <cuda_runtime.h>
#include <cuda_fp16.h>
#include <stdint.h>

#define NTOK   262144
#define NSLOT  524288
#define DIN    128
#define DOUT   128
#define NEXP   8
#define TM     128            // slot rows per tile
#define NT     (NSLOT / TM)   // 4096 tiles
#define GRID   148
#define NTHR   512
#define SAR    132            // Araw stride (floats): rows 16B-aligned, x-loads conflict-free
#define SBW    130            // Bs32 stride (floats)

typedef unsigned long long ull;

__device__ __half g_ybuf[(size_t)NSLOT * DOUT];   // gate-scaled per-slot outputs (fp16)

// ---------------------------------------------------------------------------
// helpers
// ---------------------------------------------------------------------------
__device__ __forceinline__ uint32_t smem_u32(const void* p) {
    uint32_t a;
    asm("{ .reg .u64 t; cvta.to.shared.u64 t, %1; cvt.u32.u64 %0, t; }" : "=r"(a) : "l"(p));
    return a;
}
__device__ __forceinline__ uint32_t pack_h2(float x, float y) {
    uint32_t u;
    asm("cvt.rn.f16x2.f32 %0, %1, %2;" : "=r"(u) : "f"(y), "f"(x));
    return u;
}
__device__ __forceinline__ void cp16(uint32_t dst, const void* src) {
    asm volatile("cp.async.ca.shared.global [%0], [%1], 16;" :: "r"(dst), "l"(src) : "memory");
}
#define CP_COMMIT() asm volatile("cp.async.commit_group;" ::: "memory")
#define CP_WAIT0()  asm volatile("cp.async.wait_group 0;" ::: "memory")

__device__ __forceinline__ void mma_f16(float* d, const uint32_t* a, uint32_t b0, uint32_t b1) {
    asm volatile("mma.sync.aligned.m16n8k16.row.col.f32.f16.f16.f32 "
                 "{%0,%1,%2,%3}, {%4,%5,%6,%7}, {%8,%9}, {%0,%1,%2,%3};"
                 : "+f"(d[0]), "+f"(d[1]), "+f"(d[2]), "+f"(d[3])
                 : "r"(a[0]), "r"(a[1]), "r"(a[2]), "r"(a[3]), "r"(b0), "r"(b1));
}
__device__ __forceinline__ void ffma2(ull& acc, ull x, ull w) {
    asm("fma.rn.f32x2 %0, %1, %2, %0;" : "+l"(acc) : "l"(x), "l"(w));
}

// ---------------------------------------------------------------------------
// Hybrid persistent grouped-GEMM.
//   tensor warps 0-7 : N 0..95  via fp16 HMMA (768 HMMA/tile)
//   scalar warps 8-15: N 96..127 via fp32 fma.rn.f32x2 (2 rows x 8 cols/thr)
// Araw double-buffered so the gather overlaps compute. ybuf stored fp16.
// smem: Araw f32[2][128][SAR] | As_frag uint4[2048] | B_frag uint4[1536]
//       | Bs32 f32[32][SBW]
// ---------------------------------------------------------------------------
__global__ void __launch_bounds__(NTHR, 1)
k_moe(const float* __restrict__ inputs,
      const float* __restrict__ weight,   // [E][DOUT][DIN] = W[n][k] row-major
      const float* __restrict__ gates,    // flat [NSLOT]
      const int*   __restrict__ sei,
      const int*   __restrict__ ssi)
{
    extern __shared__ float smraw[];
    float* Araw2   = smraw;                              // 2 * 128*SAR f32
    uint4* As_frag = (uint4*)(smraw + 2 * 128 * SAR);    // 2048 uint4
    uint4* B_frag  = As_frag + 2048;                     // 1536 uint4 (np 0..5)
    float* Bs32    = (float*)(B_frag + 1536);            // [32][SBW] f32 (n 96..127)

    __shared__ int   ss2[2][TM];
    __shared__ float gt2[2][TM];
    __shared__ int   ex2[2][TM];
    __shared__ int   seg_e[NEXP + 1];
    __shared__ int   seg_n;

    const int tid  = threadIdx.x;
    const int lane = tid & 31;
    const int wid  = tid >> 5;        // 0..15
    const int gr   = lane >> 2;       // 0..7
    const int tc   = lane & 3;        // 0..3
    // tensor mapping (wid 0..7): warp tile 32(M) x 48(N)
    const int wm   = wid >> 1;        // 0..3 -> rows wm*32
    const int wn   = wid & 1;         // 0..1 -> cols wn*48
    // scalar mapping (wid 8..15): thread tile rows {rg, rg+64} x cols 96+cg*8..+7
    const int tids = tid - 256;                // 0..255
    const int rg   = tids >> 2;                // 0..63
    const int cg   = tids & 3;                 // 0..3

    // ---- prologue: metadata + first A prefetch ----
    int t0 = blockIdx.x;
    if (tid < TM) {
        const int ss = ssi[t0 * TM + tid];
        ss2[0][tid] = ss;
        gt2[0][tid] = gates[ss];
        ex2[0][tid] = sei[t0 * TM + tid];
    }
    __syncthreads();
    {
        const uint32_t abase = smem_u32(Araw2);
        #pragma unroll
        for (int it = 0; it < 8; ++it) {
            const int idx = tid + NTHR * it;          // 4096 float4 units
            const int m = idx >> 5, q = (idx & 31) * 4;
            cp16(abase + (uint32_t)(m * SAR + q) * 4,
                 inputs + (size_t)(ss2[0][m] >> 1) * DIN + q);
        }
    }
    CP_COMMIT();

    int par = 0;
    int B_cur = -1;

    for (int t = t0; t < NT; t += GRID) {
        CP_WAIT0();
        __syncthreads();   // Araw[par] ready; prior tile fully done

        float* Acur = Araw2 + par * 128 * SAR;

        // ---- cvt Acur(fp32) -> As_frag(fp16 fragments), all 16 warps ----
        {
            const int R = wid >> 1;
            const int ks0 = (wid & 1) * 4;
            const int row = R * 16 + gr;
            #pragma unroll
            for (int i = 0; i < 4; ++i) {
                const int ks = ks0 + i;
                const int c0 = ks * 16 + tc * 2;
                const float2 v00 = *(const float2*)(Acur + row * SAR + c0);
                const float2 v10 = *(const float2*)(Acur + (row + 8) * SAR + c0);
                const float2 v01 = *(const float2*)(Acur + row * SAR + c0 + 8);
                const float2 v11 = *(const float2*)(Acur + (row + 8) * SAR + c0 + 8);
                uint4 f;
                f.x = pack_h2(v00.x, v00.y);
                f.y = pack_h2(v10.x, v10.y);
                f.z = pack_h2(v01.x, v01.y);
                f.w = pack_h2(v11.x, v11.y);
                As_frag[(R * 8 + ks) * 32 + lane] = f;
            }
        }

        // ---- next-tile metadata + segment list ----
        const int tn = t + GRID;
        if (tid < TM && tn < NT) {
            const int ss = ssi[tn * TM + tid];
            ss2[par ^ 1][tid] = ss;
            gt2[par ^ 1][tid] = gates[ss];
            ex2[par ^ 1][tid] = sei[tn * TM + tid];
        }
        if (tid == 0) {
            int ns = 0, e = ex2[par][0];
            seg_e[ns++] = e;
            for (int i = 1; i < TM; ++i) {
                const int ei = ex2[par][i];
                if (ei != e) { e = ei; seg_e[ns++] = e; }
            }
            seg_n = ns;
        }
        __syncthreads();   // As_frag + seg list ready; metadata[par^1] ready

        // ---- prefetch next tile's A into Araw[par^1] (overlaps compute) ----
        if (tn < NT) {
            const uint32_t abase = smem_u32(Araw2 + (par ^ 1) * 128 * SAR);
            #pragma unroll
            for (int it = 0; it < 8; ++it) {
                const int idx = tid + NTHR * it;
                const int m = idx >> 5, q = (idx & 31) * 4;
                cp16(abase + (uint32_t)(m * SAR + q) * 4,
                     inputs + (size_t)(ss2[par ^ 1][m] >> 1) * DIN + q);
            }
        }
        CP_COMMIT();

        // ---- expert segments ----
        const int nseg = seg_n;
        for (int s = 0; s < nseg; ++s) {
            const int e = seg_e[s];
            if (e != B_cur) {
                __syncthreads();   // everyone done reading old B tiles
                if (wid < 12) {
                    // warps 0-11: fp16 fragments for n8 blocks 0..11 (N 0..95)
                    const int b = wid;
                    const float* Wrow = weight + (size_t)e * DOUT * DIN + (b * 8 + gr) * DIN;
                    uint2* dst2 = (uint2*)B_frag;
                    #pragma unroll
                    for (int ks = 0; ks < 8; ++ks) {
                        const int k0 = ks * 16 + tc * 2;
                        const float2 w0 = *(const float2*)(Wrow + k0);
                        const float2 w1 = *(const float2*)(Wrow + k0 + 8);
                        uint2 f;
                        f.x = pack_h2(w0.x, w0.y);
                        f.y = pack_h2(w1.x, w1.y);
                        dst2[(((b >> 1) * 8 + ks) * 32 + lane) * 2 + (b & 1)] = f;
                    }
                } else {
                    // warps 12-15: fp32 copy of W rows 96..127 into Bs32
                    const int ws = wid - 12;
                    const float* Wb = weight + (size_t)e * DOUT * DIN;
                    #pragma unroll
                    for (int it = 0; it < 8; ++it) {
                        const int idx = lane + 32 * it;   // 256 f4 units
                        const int rl = idx >> 5, q = (idx & 31) * 4;
                        const int n = 96 + ws * 8 + rl;
                        const float4 v = *(const float4*)(Wb + n * DIN + q);
                        float* d = Bs32 + (n - 96) * SBW + q;
                        *(float2*)(d)     = make_float2(v.x, v.y);
                        *(float2*)(d + 2) = make_float2(v.z, v.w);
                    }
                }
                B_cur = e;
                __syncthreads();
            }

            if (wid < 8) {
                // ---- tensor: 32(M) x 48(N) warp tile over N 0..95 ----
                float acc[2][6][4];
                #pragma unroll
                for (int mt = 0; mt < 2; ++mt)
                    #pragma unroll
                    for (int nt = 0; nt < 6; ++nt)
                        #pragma unroll
                        for (int j = 0; j < 4; ++j) acc[mt][nt][j] = 0.f;

                const int R0  = wm * 2;
                const int np0 = wn * 3;
                #pragma unroll
                for (int ks = 0; ks < 8; ++ks) {
                    const uint4 A0 = As_frag[(R0 * 8 + ks) * 32 + lane];
                    const uint4 A1 = As_frag[((R0 + 1) * 8 + ks) * 32 + lane];
                    const uint32_t a0[4] = {A0.x, A0.y, A0.z, A0.w};
                    const uint32_t a1[4] = {A1.x, A1.y, A1.z, A1.w};
                    #pragma unroll
                    for (int j = 0; j < 3; ++j) {
                        const uint4 B = B_frag[((np0 + j) * 8 + ks) * 32 + lane];
                        mma_f16(acc[0][j * 2 + 0], a0, B.x, B.y);
                        mma_f16(acc[0][j * 2 + 1], a0, B.z, B.w);
                        mma_f16(acc[1][j * 2 + 0], a1, B.x, B.y);
                        mma_f16(acc[1][j * 2 + 1], a1, B.z, B.w);
                    }
                }

                #pragma unroll
                for (int mt = 0; mt < 2; ++mt) {
                    #pragma unroll
                    for (int half = 0; half < 2; ++half) {
                        const int m = wm * 32 + mt * 16 + gr + half * 8;
                        if (ex2[par][m] != e) continue;
                        const float g = gt2[par][m];
                        __half* dst = g_ybuf + (size_t)ss2[par][m] * DOUT + wn * 48 + 2 * tc;
                        #pragma unroll
                        for (int nt = 0; nt < 6; ++nt) {
                            const uint32_t h2 = pack_h2(acc[mt][nt][half * 2 + 0] * g,
                                                        acc[mt][nt][half * 2 + 1] * g);
                            *(uint32_t*)(dst + nt * 8) = h2;
                        }
                    }
                }
            } else {
                // ---- scalar: rows {rg, rg+64}, cols 96+cg*8..+7, fp32 ----
                ull acc2[2][8];
                #pragma unroll
                for (int r = 0; r < 2; ++r)
                    #pragma unroll
                    for (int c = 0; c < 8; ++c) acc2[r][c] = 0ull;

                const float* xrow = Acur + rg * SAR;
                const float* wrow = Bs32 + (cg * 8) * SBW;
                #pragma unroll 4
                for (int kp = 0; kp < 64; ++kp) {
                    const int k0 = kp * 2;
                    const ull x0 = *(const ull*)(xrow + k0);
                    const ull x1 = *(const ull*)(xrow + 64 * SAR + k0);
                    ull w2[8];
                    #pragma unroll
                    for (int c = 0; c < 8; ++c)
                        w2[c] = *(const ull*)(wrow + c * SBW + k0);
                    #pragma unroll
                    for (int c = 0; c < 8; ++c) {
                        ffma2(acc2[0][c], x0, w2[c]);
                        ffma2(acc2[1][c], x1, w2[c]);
                    }
                }

                #pragma unroll
                for (int r = 0; r < 2; ++r) {
                    const int m = rg + r * 64;
                    if (ex2[par][m] != e) continue;
                    const float g = gt2[par][m];
                    uint4 o;
                    {
                        const float2* a0 = (const float2*)&acc2[r][0];
                        const float2* a1 = (const float2*)&acc2[r][1];
                        const float2* a2 = (const float2*)&acc2[r][2];
                        const float2* a3 = (const float2*)&acc2[r][3];
                        const float2* a4 = (const float2*)&acc2[r][4];
                        const float2* a5 = (const float2*)&acc2[r][5];
                        const float2* a6 = (const float2*)&acc2[r][6];
                        const float2* a7 = (const float2*)&acc2[r][7];
                        o.x = pack_h2((a0->x + a0->y) * g, (a1->x + a1->y) * g);
                        o.y = pack_h2((a2->x + a2->y) * g, (a3->x + a3->y) * g);
                        o.z = pack_h2((a4->x + a4->y) * g, (a5->x + a5->y) * g);
                        o.w = pack_h2((a6->x + a6->y) * g, (a7->x + a7->y) * g);
                    }
                    __half* dst = g_ybuf + (size_t)ss2[par][m] * DOUT + 96 + cg * 8;
                    *(uint4*)dst = o;   // 16B aligned: (96+8cg)*2 bytes
                }
            }
        }

        __syncthreads();   // segment loop done before seg_e/seg_n rewritten
        par ^= 1;
    }
}

// ---------------------------------------------------------------------------
// Combine: out[t] = ybuf[2t] + ybuf[2t+1] (fp16 in, fp32 out; gates applied)
// ---------------------------------------------------------------------------
__global__ void k_combine(float* __restrict__ out) {
    const int i = blockIdx.x * 256 + threadIdx.x;   // 0 .. NTOK*32-1
    const int t = i >> 5;
    const int q = (i & 31) * 4;
    const __half2* a = (const __half2*)(g_ybuf + (size_t)(2 * t) * DOUT + q);
    const __half2* b = (const __half2*)(g_ybuf + (size_t)(2 * t + 1) * DOUT + q);
    const float2 a0 = __half22float2(a[0]);
    const float2 a1 = __half22float2(a[1]);
    const float2 b0 = __half22float2(b[0]);
    const float2 b1 = __half22float2(b[1]);
    float4 o;
    o.x = a0.x + b0.x; o.y = a0.y + b0.y;
    o.z = a1.x + b1.x; o.w = a1.y + b1.y;
    *(float4*)(out + (size_t)t * DOUT + q) = o;
}

// ---------------------------------------------------------------------------
extern "C" void kernel_launch(void* const* d_in, const int* in_sizes, int n_in,
                              void* d_out, int out_size)
{
    const float* inputs = (const float*)d_in[0];
    const float* weight = (const float*)d_in[1];
    const float* gates  = (const float*)d_in[2];

    int idxs[2] = {-1, -1};
    int found = 0;
    for (int i = 3; i < n_in && found < 2; ++i) {
        if (in_sizes[i] == 1) continue;   // scalar k
        idxs[found++] = i;
    }
    const int* sei = (const int*)d_in[idxs[0]];
    const int* ssi = (const int*)d_in[idxs[1]];
    float* out = (float*)d_out;
    (void)out_size;

    // Araw2 135168 + As_frag 32768 + B_frag 24576 + Bs32 16640 = 209152
    const int smem = 2 * 128 * SAR * 4 + 2048 * 16 + 1536 * 16 + 32 * SBW * 4;
    cudaFuncSetAttribute(k_moe, cudaFuncAttributeMaxDynamicSharedMemorySize, smem);

    k_moe<<<GRID, NTHR, smem>>>(inputs, weight, gates, sei, ssi);
    k_combine<<<(NTOK * 32) / 256, 256>>>(out);
}

// round 9
// speedup vs baseline: 2.9846x; 1.9076x over previous
#include <cuda_runtime.h>
#include <cuda_fp16.h>
#include <stdint.h>

#define NTOK   262144
#define NSLOT  524288
#define DIN    128
#define DOUT   128
#define NEXP   8
#define TM     128            // slot rows per tile
#define NT     (NSLOT / TM)   // 4096 tiles
#define GRID   148
#define NTHR   512
#define SAR    132            // Araw padded stride (floats)

typedef unsigned long long ull;

__device__ __half g_ybuf[(size_t)NSLOT * DOUT];   // gate-scaled per-slot outputs (fp16)

// ---------------------------------------------------------------------------
// helpers
// ---------------------------------------------------------------------------
__device__ __forceinline__ uint32_t smem_u32(const void* p) {
    uint32_t a;
    asm("{ .reg .u64 t; cvta.to.shared.u64 t, %1; cvt.u32.u64 %0, t; }" : "=r"(a) : "l"(p));
    return a;
}
// pack two fp32 -> fp16x2 (lo = x, hi = y)
__device__ __forceinline__ uint32_t pack_h2(float x, float y) {
    uint32_t u;
    asm("cvt.rn.f16x2.f32 %0, %1, %2;" : "=r"(u) : "f"(y), "f"(x));
    return u;
}
__device__ __forceinline__ void cp16(uint32_t dst, const void* src) {
    asm volatile("cp.async.ca.shared.global [%0], [%1], 16;" :: "r"(dst), "l"(src) : "memory");
}
#define CP_COMMIT() asm volatile("cp.async.commit_group;" ::: "memory")
#define CP_WAIT0()  asm volatile("cp.async.wait_group 0;" ::: "memory")

// m16n8k16 fp16 -> fp32 acc
__device__ __forceinline__ void mma_f16(float* d, const uint32_t* a, uint32_t b0, uint32_t b1) {
    asm volatile("mma.sync.aligned.m16n8k16.row.col.f32.f16.f16.f32 "
                 "{%0,%1,%2,%3}, {%4,%5,%6,%7}, {%8,%9}, {%0,%1,%2,%3};"
                 : "+f"(d[0]), "+f"(d[1]), "+f"(d[2]), "+f"(d[3])
                 : "r"(a[0]), "r"(a[1]), "r"(a[2]), "r"(a[3]), "r"(b0), "r"(b1));
}

// ---------------------------------------------------------------------------
// Persistent grouped-GEMM (fp16 mma.sync, fragment-major smem), 512 threads.
// smem: Araw fp32 [128][SAR] | As_frag uint4[8*8*32] | B_frag uint4[8*8*32]
//   As_frag[R(16-row blk)][ks][lane] = {a0,a1,a2,a3}
//   B_frag [np(16-n blk)][ks][lane]  = {b0,b1 of n8 blk 2np, b0,b1 of 2np+1}
// ---------------------------------------------------------------------------
__global__ void __launch_bounds__(NTHR, 1)
k_moe(const float* __restrict__ inputs,
      const float* __restrict__ weight,   // [E][DOUT][DIN] == W[n][k] row-major
      const float* __restrict__ gates,    // flat [NSLOT]
      const int*   __restrict__ sei,
      const int*   __restrict__ ssi)
{
    extern __shared__ float smraw[];
    float* Araw   = smraw;                                   // 128*SAR f32
    uint4* As_frag = (uint4*)(smraw + 128 * SAR);            // 2048 uint4
    uint4* B_frag  = As_frag + 8 * 8 * 32;                   // 2048 uint4

    __shared__ int   ss2[2][TM];
    __shared__ float gt2[2][TM];
    __shared__ int   ex2[2][TM];
    __shared__ int   seg_e[NEXP + 1];
    __shared__ int   seg_n;

    const int tid  = threadIdx.x;
    const int lane = tid & 31;
    const int wid  = tid >> 5;        // 0..15
    const int wm   = wid >> 2;        // 0..3  -> rows wm*32
    const int wn   = wid & 3;         // 0..3  -> cols wn*32
    const int gr   = lane >> 2;       // 0..7
    const int tc   = lane & 3;        // 0..3

    // ---- prologue: metadata + first A prefetch ----
    int t0 = blockIdx.x;
    if (tid < TM) {
        const int ss = ssi[t0 * TM + tid];
        ss2[0][tid] = ss;
        gt2[0][tid] = gates[ss];
        ex2[0][tid] = sei[t0 * TM + tid];
    }
    __syncthreads();
    {
        const uint32_t abase = smem_u32(Araw);
        #pragma unroll
        for (int it = 0; it < 8; ++it) {
            const int idx = tid + NTHR * it;          // 4096 float4 units
            const int m = idx >> 5, q = (idx & 31) * 4;
            cp16(abase + (uint32_t)(m * SAR + q) * 4,
                 inputs + (size_t)(ss2[0][m] >> 1) * DIN + q);
        }
    }
    CP_COMMIT();

    int par = 0;
    int B_cur = -1;

    for (int t = t0; t < NT; t += GRID) {
        CP_WAIT0();
        __syncthreads();   // Araw ready; prior-tile MMA done with As_frag

        // ---- cvt Araw(fp32) -> As_frag(fp16 fragments) ----
        // warp w: R = w>>1, ks in 4*(w&1) .. +3
        {
            const int R = wid >> 1;
            const int ks0 = (wid & 1) * 4;
            const int row = R * 16 + gr;
            #pragma unroll
            for (int i = 0; i < 4; ++i) {
                const int ks = ks0 + i;
                const int c0 = ks * 16 + tc * 2;
                const float2 v00 = *(const float2*)(Araw + row * SAR + c0);
                const float2 v10 = *(const float2*)(Araw + (row + 8) * SAR + c0);
                const float2 v01 = *(const float2*)(Araw + row * SAR + c0 + 8);
                const float2 v11 = *(const float2*)(Araw + (row + 8) * SAR + c0 + 8);
                uint4 f;
                f.x = pack_h2(v00.x, v00.y);
                f.y = pack_h2(v10.x, v10.y);
                f.z = pack_h2(v01.x, v01.y);
                f.w = pack_h2(v11.x, v11.y);
                As_frag[(R * 8 + ks) * 32 + lane] = f;
            }
        }
        __syncthreads();   // Araw free, As_frag ready

        // ---- next-tile metadata + segment list ----
        const int tn = t + GRID;
        if (tid < TM && tn < NT) {
            const int ss = ssi[tn * TM + tid];
            ss2[par ^ 1][tid] = ss;
            gt2[par ^ 1][tid] = gates[ss];
            ex2[par ^ 1][tid] = sei[tn * TM + tid];
        }
        if (tid == 0) {
            int ns = 0, e = ex2[par][0];
            seg_e[ns++] = e;
            for (int i = 1; i < TM; ++i) {
                const int ei = ex2[par][i];
                if (ei != e) { e = ei; seg_e[ns++] = e; }
            }
            seg_n = ns;
        }
        __syncthreads();

        // ---- prefetch next tile's A into Araw ----
        if (tn < NT) {
            const uint32_t abase = smem_u32(Araw);
            #pragma unroll
            for (int it = 0; it < 8; ++it) {
                const int idx = tid + NTHR * it;
                const int m = idx >> 5, q = (idx & 31) * 4;
                cp16(abase + (uint32_t)(m * SAR + q) * 4,
                     inputs + (size_t)(ss2[par ^ 1][m] >> 1) * DIN + q);
            }
        }
        CP_COMMIT();

        // ---- expert segments ----
        const int nseg = seg_n;
        for (int s = 0; s < nseg; ++s) {
            const int e = seg_e[s];
            if (e != B_cur) {
                __syncthreads();   // all warps done reading old B_frag
                // warp w converts n8 block b = w
                const int b = wid;
                const float* Wrow = weight + (size_t)e * DOUT * DIN + (b * 8 + gr) * DIN;
                uint2* dst2 = (uint2*)B_frag;   // 2 uint2 per uint4
                #pragma unroll
                for (int ks = 0; ks < 8; ++ks) {
                    const int k0 = ks * 16 + tc * 2;
                    const float2 w0 = *(const float2*)(Wrow + k0);
                    const float2 w1 = *(const float2*)(Wrow + k0 + 8);
                    uint2 f;
                    f.x = pack_h2(w0.x, w0.y);
                    f.y = pack_h2(w1.x, w1.y);
                    dst2[(((b >> 1) * 8 + ks) * 32 + lane) * 2 + (b & 1)] = f;
                }
                B_cur = e;
                __syncthreads();
            }

            // ---- MMA: warp tile 32(M) x 32(N), K=128, 8 ks slices ----
            float acc[2][4][4];
            #pragma unroll
            for (int mt = 0; mt < 2; ++mt)
                #pragma unroll
                for (int nt = 0; nt < 4; ++nt)
                    #pragma unroll
                    for (int j = 0; j < 4; ++j) acc[mt][nt][j] = 0.f;

            const int R0  = wm * 2;
            const int np0 = wn * 2;
            #pragma unroll
            for (int ks = 0; ks < 8; ++ks) {
                const uint4 A0 = As_frag[(R0 * 8 + ks) * 32 + lane];
                const uint4 A1 = As_frag[((R0 + 1) * 8 + ks) * 32 + lane];
                const uint4 B0 = B_frag[(np0 * 8 + ks) * 32 + lane];
                const uint4 B1 = B_frag[((np0 + 1) * 8 + ks) * 32 + lane];
                const uint32_t a0[4] = {A0.x, A0.y, A0.z, A0.w};
                const uint32_t a1[4] = {A1.x, A1.y, A1.z, A1.w};
                mma_f16(acc[0][0], a0, B0.x, B0.y);
                mma_f16(acc[0][1], a0, B0.z, B0.w);
                mma_f16(acc[0][2], a0, B1.x, B1.y);
                mma_f16(acc[0][3], a0, B1.z, B1.w);
                mma_f16(acc[1][0], a1, B0.x, B0.y);
                mma_f16(acc[1][1], a1, B0.z, B0.w);
                mma_f16(acc[1][2], a1, B1.x, B1.y);
                mma_f16(acc[1][3], a1, B1.z, B1.w);
            }

            // ---- epilogue: gate-scale + scatter rows (fp16 packed) ----
            #pragma unroll
            for (int mt = 0; mt < 2; ++mt) {
                #pragma unroll
                for (int half = 0; half < 2; ++half) {
                    const int m = wm * 32 + mt * 16 + gr + half * 8;
                    if (ex2[par][m] != e) continue;
                    const float g = gt2[par][m];
                    __half* dst = g_ybuf + (size_t)ss2[par][m] * DOUT + wn * 32 + 2 * tc;
                    #pragma unroll
                    for (int nt = 0; nt < 4; ++nt) {
                        const uint32_t h2 = pack_h2(acc[mt][nt][half * 2 + 0] * g,
                                                    acc[mt][nt][half * 2 + 1] * g);
                        *(uint32_t*)(dst + nt * 8) = h2;
                    }
                }
            }
        }

        par ^= 1;
        __syncthreads();   // epilogue done before buffers flip
    }
}

// ---------------------------------------------------------------------------
// Combine: out[t] = ybuf[2t] + ybuf[2t+1] (fp16 in, fp32 out; gates applied)
// ---------------------------------------------------------------------------
__global__ void k_combine(float* __restrict__ out) {
    const int i = blockIdx.x * 256 + threadIdx.x;   // 0 .. NTOK*32-1
    const int t = i >> 5;
    const int q = (i & 31) * 4;
    const __half2* a = (const __half2*)(g_ybuf + (size_t)(2 * t) * DOUT + q);
    const __half2* b = (const __half2*)(g_ybuf + (size_t)(2 * t + 1) * DOUT + q);
    const float2 a0 = __half22float2(a[0]);
    const float2 a1 = __half22float2(a[1]);
    const float2 b0 = __half22float2(b[0]);
    const float2 b1 = __half22float2(b[1]);
    float4 o;
    o.x = a0.x + b0.x; o.y = a0.y + b0.y;
    o.z = a1.x + b1.x; o.w = a1.y + b1.y;
    *(float4*)(out + (size_t)t * DOUT + q) = o;
}

// ---------------------------------------------------------------------------
extern "C" void kernel_launch(void* const* d_in, const int* in_sizes, int n_in,
                              void* d_out, int out_size)
{
    const float* inputs = (const float*)d_in[0];
    const float* weight = (const float*)d_in[1];
    const float* gates  = (const float*)d_in[2];

    int idxs[2] = {-1, -1};
    int found = 0;
    for (int i = 3; i < n_in && found < 2; ++i) {
        if (in_sizes[i] == 1) continue;   // scalar k
        idxs[found++] = i;
    }
    const int* sei = (const int*)d_in[idxs[0]];
    const int* ssi = (const int*)d_in[idxs[1]];
    float* out = (float*)d_out;
    (void)out_size;

    const int smem = 128 * SAR * 4 + 2 * 2048 * 16;   // 67584 + 65536 = 133120
    cudaFuncSetAttribute(k_moe, cudaFuncAttributeMaxDynamicSharedMemorySize, smem);

    k_moe<<<GRID, NTHR, smem>>>(inputs, weight, gates, sei, ssi);
    k_combine<<<(NTOK * 32) / 256, 256>>>(out);
}